// round 4
// baseline (speedup 1.0000x reference)
#include <cuda_runtime.h>
#include <cuda_bf16.h>

// Renderer: B=2, N=2048 points, S=128 image, K=16 per pixel, alpha composite.
//
// Scatter-binning approach:
//   K1 (project+bin): project each point to NDC; if visible, push
//       (x, y, z, idx) into the per-tile candidate list of every 8x8-pixel
//       tile its radius-R footprint overlaps (at most 2x2 tiles).
//   K2 (render): one 64-thread block per tile; each thread = one pixel,
//       z-buffers only the tile's candidates (avg ~10), composites, and the
//       block re-zeroes its tile counter so state returns to zero each call
//       (graph-replay deterministic).
// Insertion sort keys on (z, index): deterministic under atomic push order
// and matches top_k's index-stable tie-breaking.

#define S_IMG    128
#define NPTS     2048
#define KHITS    16
#define RADIUS   0.02f
#define RAD2     (RADIUS * RADIUS)
#define INV_RAD2 (1.0f / RAD2)
#define ZNEAR    1.0f
#define FOCAL    1.7320508075688772f   // 1 / tan(30 deg)
#define TILE     8
#define TILES_X  (S_IMG / TILE)        // 16
#define NTILES   (TILES_X * TILES_X)   // 256 per batch
#define B_MAX    2
#define CAP      1024                  // >> worst expected ~139 per tile

__device__ int    g_cnt [B_MAX * NTILES];           // zero at steady state
__device__ float4 g_list[B_MAX * NTILES * CAP];     // (x, y, z, idx) ~8MB

// ------------------------------------------------------------ project+bin --
__global__ __launch_bounds__(256) void project_bin_kernel(
    const float* __restrict__ points,   // [B, N, 3]
    const float* __restrict__ eye)      // [B, 3]
{
    const int g = blockIdx.x * blockDim.x + threadIdx.x;
    const int b = g / NPTS;
    const int i = g - b * NPTS;

    const float ex = eye[b * 3 + 0];
    const float ey = eye[b * 3 + 1];
    const float ez = eye[b * 3 + 2];

    // camera basis (look-at origin, up = +y)
    float zn  = rsqrtf(ex * ex + ey * ey + ez * ez);
    float zax = -ex * zn, zay = -ey * zn, zaz = -ez * zn;
    float xax = zaz, xaz = -zax;                 // up x z (x.y == 0)
    float xn  = rsqrtf(xax * xax + xaz * xaz);
    xax *= xn; xaz *= xn;
    float yax = zay * xaz;
    float yay = zaz * xax - zax * xaz;
    float yaz = -zay * xax;

    const float* p = points + (size_t)g * 3;
    float dx = p[0] - ex, dy = p[1] - ey, dz = p[2] - ez;
    float cz = dx * zax + dy * zay + dz * zaz;
    if (cz <= ZNEAR) return;

    float cx = dx * xax + dz * xaz;
    float cy = dx * yax + dy * yay + dz * yaz;
    float s  = FOCAL / cz;
    float x  = cx * s;
    float y  = cy * s;

    // pixel-space footprint: column c center at px = 1-(2c+1)/S, i.e.
    // c = (1 - px)*S/2 - 0.5. Over-inclusive floor/ceil bounds are fine.
    float c_lo = (1.0f - x - RADIUS) * (S_IMG * 0.5f) - 0.5f;
    float c_hi = (1.0f - x + RADIUS) * (S_IMG * 0.5f) - 0.5f;
    float r_lo = (1.0f - y - RADIUS) * (S_IMG * 0.5f) - 0.5f;
    float r_hi = (1.0f - y + RADIUS) * (S_IMG * 0.5f) - 0.5f;
    if (c_hi < 0.0f || c_lo > (float)(S_IMG - 1) ||
        r_hi < 0.0f || r_lo > (float)(S_IMG - 1)) return;

    int cmin = max(0,         (int)floorf(c_lo));
    int cmax = min(S_IMG - 1, (int)ceilf (c_hi));
    int rmin = max(0,         (int)floorf(r_lo));
    int rmax = min(S_IMG - 1, (int)ceilf (r_hi));

    int txmin = cmin >> 3, txmax = cmax >> 3;
    int tymin = rmin >> 3, tymax = rmax >> 3;

    float4 e = make_float4(x, y, cz, __int_as_float(i));
    for (int ty = tymin; ty <= tymax; ty++) {
        for (int tx = txmin; tx <= txmax; tx++) {
            int t = (b * NTILES) + ty * TILES_X + tx;
            int slot = atomicAdd(&g_cnt[t], 1);
            if (slot < CAP) g_list[(size_t)t * CAP + slot] = e;
        }
    }
}

// ----------------------------------------------------------------- render --
__global__ __launch_bounds__(64) void render_tiled_kernel(
    const float* __restrict__ colors,   // [B, N, 3]
    float* __restrict__ out)            // [B, S, S, 3]
{
    const int b   = blockIdx.z;
    const int tcx = blockIdx.x;
    const int tcy = blockIdx.y;
    const int tid = threadIdx.x;        // 0..63

    const int t   = (b * NTILES) + tcy * TILES_X + tcx;
    const int cnt = min(g_cnt[t], CAP);
    __syncthreads();
    if (tid == 0) g_cnt[t] = 0;         // restore zero state for next call

    const float4* __restrict__ list = g_list + (size_t)t * CAP;

    // this thread's pixel
    const int col = tcx * TILE + (tid & (TILE - 1));
    const int row = tcy * TILE + (tid >> 3);
    const float inv = 1.0f / (float)S_IMG;
    const float pxc = 1.0f - (2.0f * col + 1.0f) * inv;
    const float pyc = 1.0f - (2.0f * row + 1.0f) * inv;

    // K nearest-in-depth hits, keyed (z, index)
    float zb[KHITS];
    float db[KHITS];
    int   ib[KHITS];
    int   nh = 0;

    for (int j = 0; j < cnt; j++) {
        float4 q = __ldg(&list[j]);
        float ddx = pxc - q.x;
        float ddy = pyc - q.y;
        float d2  = ddx * ddx + ddy * ddy;
        if (d2 < RAD2) {
            float z = q.z;
            int   i = __float_as_int(q.w);
            if (nh < KHITS) {
                int k = nh++;
                while (k > 0 && (zb[k-1] > z || (zb[k-1] == z && ib[k-1] > i))) {
                    zb[k] = zb[k-1]; db[k] = db[k-1]; ib[k] = ib[k-1]; k--;
                }
                zb[k] = z; db[k] = d2; ib[k] = i;
            } else if (z < zb[KHITS-1] ||
                       (z == zb[KHITS-1] && i < ib[KHITS-1])) {
                int k = KHITS - 1;
                while (k > 0 && (zb[k-1] > z || (zb[k-1] == z && ib[k-1] > i))) {
                    zb[k] = zb[k-1]; db[k] = db[k-1]; ib[k] = ib[k-1]; k--;
                }
                zb[k] = z; db[k] = d2; ib[k] = i;
            }
        }
    }

    // front-to-back alpha compositing
    float T = 1.0f, r = 0.0f, g = 0.0f, bl = 0.0f;
    for (int k = 0; k < nh; k++) {
        float a = 1.0f - db[k] * INV_RAD2;
        a = fminf(fmaxf(a, 0.0f), 1.0f);
        const float* c = colors + (size_t)(b * NPTS + ib[k]) * 3;
        float w = a * T;
        r  += w * c[0];
        g  += w * c[1];
        bl += w * c[2];
        T *= (1.0f - a);
    }

    float* o = out + (size_t)((b * S_IMG + row) * S_IMG + col) * 3;
    o[0] = r; o[1] = g; o[2] = bl;
}

// ----------------------------------------------------------------- launch ---
extern "C" void kernel_launch(void* const* d_in, const int* in_sizes, int n_in,
                              void* d_out, int out_size) {
    const float* points = (const float*)d_in[0];
    const float* eye    = (const float*)d_in[1];
    const float* colors = (const float*)d_in[2];
    float* out          = (float*)d_out;

    const int B = in_sizes[1] / 3;     // eye is [B,3]

    project_bin_kernel<<<(B * NPTS) / 256, 256>>>(points, eye);

    dim3 grid(TILES_X, TILES_X, B);
    render_tiled_kernel<<<grid, 64>>>(colors, out);
}

// round 5
// speedup vs baseline: 1.4122x; 1.4122x over previous
#include <cuda_runtime.h>
#include <cuda_bf16.h>

// Renderer: B=2, N=2048 points, S=128 image, K=16 per pixel, alpha composite.
//
// Scatter-binning + smem staging:
//   K1 (project+bin): project each point to NDC; if visible, push
//       (x, y, z, idx) into the per-tile candidate list of every 8x8-pixel
//       tile its radius-R footprint overlaps (at most 2x2 tiles).
//   K2 (render): one 64-thread block per tile. Block stages its candidate
//       list into shared memory with parallel loads (hides L2 latency),
//       then each thread (one pixel) z-buffers the smem candidates and
//       composites. Empty tiles exit immediately. The block re-zeroes its
//       tile counter so device state returns to zero each call.
// Insertion sort keys on (z, index): deterministic under atomic push order
// and matches top_k's index-stable tie-breaking.

#define S_IMG    128
#define NPTS     2048
#define KHITS    16
#define RADIUS   0.02f
#define RAD2     (RADIUS * RADIUS)
#define INV_RAD2 (1.0f / RAD2)
#define ZNEAR    1.0f
#define FOCAL    1.7320508075688772f   // 1 / tan(30 deg)
#define TILE     8
#define TILES_X  (S_IMG / TILE)        // 16
#define NTILES   (TILES_X * TILES_X)   // 256 per batch
#define B_MAX    2
#define CAP      256                   // worst expected ~140 per tile

__device__ int    g_cnt [B_MAX * NTILES];           // zero at steady state
__device__ float4 g_list[B_MAX * NTILES * CAP];     // (x, y, z, idx) ~2MB

// ------------------------------------------------------------ project+bin --
__global__ __launch_bounds__(256) void project_bin_kernel(
    const float* __restrict__ points,   // [B, N, 3]
    const float* __restrict__ eye)      // [B, 3]
{
    const int g = blockIdx.x * blockDim.x + threadIdx.x;
    const int b = g / NPTS;
    const int i = g - b * NPTS;

    const float ex = eye[b * 3 + 0];
    const float ey = eye[b * 3 + 1];
    const float ez = eye[b * 3 + 2];

    // camera basis (look-at origin, up = +y)
    float zn  = rsqrtf(ex * ex + ey * ey + ez * ez);
    float zax = -ex * zn, zay = -ey * zn, zaz = -ez * zn;
    float xax = zaz, xaz = -zax;                 // up x z (x.y == 0)
    float xn  = rsqrtf(xax * xax + xaz * xaz);
    xax *= xn; xaz *= xn;
    float yax = zay * xaz;
    float yay = zaz * xax - zax * xaz;
    float yaz = -zay * xax;

    const float* p = points + (size_t)g * 3;
    float dx = p[0] - ex, dy = p[1] - ey, dz = p[2] - ez;
    float cz = dx * zax + dy * zay + dz * zaz;
    if (cz <= ZNEAR) return;

    float cx = dx * xax + dz * xaz;
    float cy = dx * yax + dy * yay + dz * yaz;
    float s  = FOCAL / cz;
    float x  = cx * s;
    float y  = cy * s;

    // pixel-space footprint: column c center at px = 1-(2c+1)/S, i.e.
    // c = (1 - px)*S/2 - 0.5. Over-inclusive floor/ceil bounds are fine.
    float c_lo = (1.0f - x - RADIUS) * (S_IMG * 0.5f) - 0.5f;
    float c_hi = (1.0f - x + RADIUS) * (S_IMG * 0.5f) - 0.5f;
    float r_lo = (1.0f - y - RADIUS) * (S_IMG * 0.5f) - 0.5f;
    float r_hi = (1.0f - y + RADIUS) * (S_IMG * 0.5f) - 0.5f;
    if (c_hi < 0.0f || c_lo > (float)(S_IMG - 1) ||
        r_hi < 0.0f || r_lo > (float)(S_IMG - 1)) return;

    int cmin = max(0,         (int)floorf(c_lo));
    int cmax = min(S_IMG - 1, (int)ceilf (c_hi));
    int rmin = max(0,         (int)floorf(r_lo));
    int rmax = min(S_IMG - 1, (int)ceilf (r_hi));

    int txmin = cmin >> 3, txmax = cmax >> 3;
    int tymin = rmin >> 3, tymax = rmax >> 3;

    float4 e = make_float4(x, y, cz, __int_as_float(i));
    for (int ty = tymin; ty <= tymax; ty++) {
        for (int tx = txmin; tx <= txmax; tx++) {
            int t = (b * NTILES) + ty * TILES_X + tx;
            int slot = atomicAdd(&g_cnt[t], 1);
            if (slot < CAP) g_list[(size_t)t * CAP + slot] = e;
        }
    }
}

// ----------------------------------------------------------------- render --
__global__ __launch_bounds__(64) void render_tiled_kernel(
    const float* __restrict__ colors,   // [B, N, 3]
    float* __restrict__ out)            // [B, S, S, 3]
{
    __shared__ float4 sl[CAP];

    const int b   = blockIdx.z;
    const int tcx = blockIdx.x;
    const int tcy = blockIdx.y;
    const int tid = threadIdx.x;        // 0..63

    const int t   = (b * NTILES) + tcy * TILES_X + tcx;
    const int cnt = min(g_cnt[t], CAP);

    // this thread's pixel
    const int col = tcx * TILE + (tid & (TILE - 1));
    const int row = tcy * TILE + (tid >> 3);
    float* o = out + (size_t)((b * S_IMG + row) * S_IMG + col) * 3;

    if (cnt == 0) {                      // fast path: majority of tiles
        if (tid == 0) g_cnt[t] = 0;
        o[0] = 0.0f; o[1] = 0.0f; o[2] = 0.0f;
        return;
    }

    // stage candidate list into shared memory (parallel loads, high MLP)
    const float4* __restrict__ list = g_list + (size_t)t * CAP;
    for (int j = tid; j < cnt; j += 64) sl[j] = __ldg(&list[j]);
    __syncthreads();
    if (tid == 0) g_cnt[t] = 0;         // restore zero state for next call

    const float inv = 1.0f / (float)S_IMG;
    const float pxc = 1.0f - (2.0f * col + 1.0f) * inv;
    const float pyc = 1.0f - (2.0f * row + 1.0f) * inv;

    // K nearest-in-depth hits, keyed (z, index)
    float zb[KHITS];
    float db[KHITS];
    int   ib[KHITS];
    int   nh = 0;

    for (int j = 0; j < cnt; j++) {
        float4 q = sl[j];
        float ddx = pxc - q.x;
        float ddy = pyc - q.y;
        float d2  = ddx * ddx + ddy * ddy;
        if (d2 < RAD2) {
            float z = q.z;
            int   i = __float_as_int(q.w);
            if (nh < KHITS) {
                int k = nh++;
                while (k > 0 && (zb[k-1] > z || (zb[k-1] == z && ib[k-1] > i))) {
                    zb[k] = zb[k-1]; db[k] = db[k-1]; ib[k] = ib[k-1]; k--;
                }
                zb[k] = z; db[k] = d2; ib[k] = i;
            } else if (z < zb[KHITS-1] ||
                       (z == zb[KHITS-1] && i < ib[KHITS-1])) {
                int k = KHITS - 1;
                while (k > 0 && (zb[k-1] > z || (zb[k-1] == z && ib[k-1] > i))) {
                    zb[k] = zb[k-1]; db[k] = db[k-1]; ib[k] = ib[k-1]; k--;
                }
                zb[k] = z; db[k] = d2; ib[k] = i;
            }
        }
    }

    // front-to-back alpha compositing
    float T = 1.0f, r = 0.0f, g = 0.0f, bl = 0.0f;
    for (int k = 0; k < nh; k++) {
        float a = 1.0f - db[k] * INV_RAD2;
        a = fminf(fmaxf(a, 0.0f), 1.0f);
        const float* c = colors + (size_t)(b * NPTS + ib[k]) * 3;
        float w = a * T;
        r  += w * c[0];
        g  += w * c[1];
        bl += w * c[2];
        T *= (1.0f - a);
    }

    o[0] = r; o[1] = g; o[2] = bl;
}

// ----------------------------------------------------------------- launch ---
extern "C" void kernel_launch(void* const* d_in, const int* in_sizes, int n_in,
                              void* d_out, int out_size) {
    const float* points = (const float*)d_in[0];
    const float* eye    = (const float*)d_in[1];
    const float* colors = (const float*)d_in[2];
    float* out          = (float*)d_out;

    const int B = in_sizes[1] / 3;     // eye is [B,3]

    project_bin_kernel<<<(B * NPTS) / 256, 256>>>(points, eye);

    dim3 grid(TILES_X, TILES_X, B);
    render_tiled_kernel<<<grid, 64>>>(colors, out);
}

// round 9
// speedup vs baseline: 1.7625x; 1.2480x over previous
#include <cuda_runtime.h>
#include <cuda_bf16.h>

// Renderer: B=2, N=2048 points, S=128 image, K=16 per pixel, alpha composite.
//
// Scatter-binning + smem staging + deferred sort:
//   K1 (project+bin): project each point to NDC; if visible, push
//       (x, y, z, idx) into the per-tile candidate list of every 8x8-pixel
//       tile its radius-R footprint overlaps.
//   K2 (render): one 64-thread block per tile. Block stages its candidate
//       list into shared memory, then each thread (one pixel) runs a
//       branch-light hit-collection loop (no sorting inside), sorts the few
//       collected hits once by (z, index), and alpha-composites. Empty tiles
//       exit immediately. The block re-zeroes its tile counter so device
//       state returns to zero each call (graph-replay deterministic).
// Sort keyed on (z, index): deterministic under atomic push order and
// matches top_k's index-stable tie-breaking.

#define S_IMG    128
#define NPTS     2048
#define KHITS    16
#define HCAP     20                    // hit buffer; prune to 16 if it fills
#define RADIUS   0.02f
#define RAD2     (RADIUS * RADIUS)
#define INV_RAD2 (1.0f / RAD2)
#define ZNEAR    1.0f
#define FOCAL    1.7320508075688772f   // 1 / tan(30 deg)
#define TILE     8
#define TILES_X  (S_IMG / TILE)        // 16
#define NTILES   (TILES_X * TILES_X)   // 256 per batch
#define B_MAX    2
#define CAP      256                   // worst expected ~100 per tile

__device__ int    g_cnt [B_MAX * NTILES];           // zero at steady state
__device__ float4 g_list[B_MAX * NTILES * CAP];     // (x, y, z, idx) ~2MB

// ------------------------------------------------------------ project+bin --
__global__ __launch_bounds__(256) void project_bin_kernel(
    const float* __restrict__ points,   // [B, N, 3]
    const float* __restrict__ eye)      // [B, 3]
{
    const int g = blockIdx.x * blockDim.x + threadIdx.x;
    const int b = g / NPTS;
    const int i = g - b * NPTS;

    const float ex = eye[b * 3 + 0];
    const float ey = eye[b * 3 + 1];
    const float ez = eye[b * 3 + 2];

    // camera basis (look-at origin, up = +y)
    float zn  = rsqrtf(ex * ex + ey * ey + ez * ez);
    float zax = -ex * zn, zay = -ey * zn, zaz = -ez * zn;
    float xax = zaz, xaz = -zax;                 // up x z (x.y == 0)
    float xn  = rsqrtf(xax * xax + xaz * xaz);
    xax *= xn; xaz *= xn;
    float yax = zay * xaz;
    float yay = zaz * xax - zax * xaz;
    float yaz = -zay * xax;

    const float* p = points + (size_t)g * 3;
    float dx = p[0] - ex, dy = p[1] - ey, dz = p[2] - ez;
    float cz = dx * zax + dy * zay + dz * zaz;
    if (cz <= ZNEAR) return;

    float cx = dx * xax + dz * xaz;
    float cy = dx * yax + dy * yay + dz * yaz;
    float s  = FOCAL / cz;
    float x  = cx * s;
    float y  = cy * s;

    // pixel-space footprint: column c center at px = 1-(2c+1)/S, i.e.
    // c = (1 - px)*S/2 - 0.5. Over-inclusive floor/ceil bounds are fine.
    float c_lo = (1.0f - x - RADIUS) * (S_IMG * 0.5f) - 0.5f;
    float c_hi = (1.0f - x + RADIUS) * (S_IMG * 0.5f) - 0.5f;
    float r_lo = (1.0f - y - RADIUS) * (S_IMG * 0.5f) - 0.5f;
    float r_hi = (1.0f - y + RADIUS) * (S_IMG * 0.5f) - 0.5f;
    if (c_hi < 0.0f || c_lo > (float)(S_IMG - 1) ||
        r_hi < 0.0f || r_lo > (float)(S_IMG - 1)) return;

    int cmin = max(0,         (int)floorf(c_lo));
    int cmax = min(S_IMG - 1, (int)ceilf (c_hi));
    int rmin = max(0,         (int)floorf(r_lo));
    int rmax = min(S_IMG - 1, (int)ceilf (r_hi));

    int txmin = cmin >> 3, txmax = cmax >> 3;
    int tymin = rmin >> 3, tymax = rmax >> 3;

    float4 e = make_float4(x, y, cz, __int_as_float(i));
    for (int ty = tymin; ty <= tymax; ty++) {
        for (int tx = txmin; tx <= txmax; tx++) {
            int t = (b * NTILES) + ty * TILES_X + tx;
            int slot = atomicAdd(&g_cnt[t], 1);
            if (slot < CAP) g_list[(size_t)t * CAP + slot] = e;
        }
    }
}

// -------- sort nh hits ascending by (z, idx); insertion sort (nh small) ----
__device__ __forceinline__ void sort_hits(float* hz, float* hd, int* hi, int nh)
{
    for (int a = 1; a < nh; a++) {
        float z = hz[a], d = hd[a];
        int   i = hi[a];
        int k = a;
        while (k > 0 && (hz[k-1] > z || (hz[k-1] == z && hi[k-1] > i))) {
            hz[k] = hz[k-1]; hd[k] = hd[k-1]; hi[k] = hi[k-1]; k--;
        }
        hz[k] = z; hd[k] = d; hi[k] = i;
    }
}

// ----------------------------------------------------------------- render --
__global__ __launch_bounds__(64) void render_tiled_kernel(
    const float* __restrict__ colors,   // [B, N, 3]
    float* __restrict__ out)            // [B, S, S, 3]
{
    __shared__ float4 sl[CAP];

    const int b   = blockIdx.z;
    const int tcx = blockIdx.x;
    const int tcy = blockIdx.y;
    const int tid = threadIdx.x;        // 0..63

    const int t   = (b * NTILES) + tcy * TILES_X + tcx;
    const int cnt = min(g_cnt[t], CAP);

    // this thread's pixel
    const int col = tcx * TILE + (tid & (TILE - 1));
    const int row = tcy * TILE + (tid >> 3);
    float* o = out + (size_t)((b * S_IMG + row) * S_IMG + col) * 3;

    if (cnt == 0) {                      // fast path: majority of tiles
        if (tid == 0) g_cnt[t] = 0;
        o[0] = 0.0f; o[1] = 0.0f; o[2] = 0.0f;
        return;
    }

    // stage candidate list into shared memory (parallel loads, high MLP)
    const float4* __restrict__ list = g_list + (size_t)t * CAP;
    for (int j = tid; j < cnt; j += 64) sl[j] = __ldg(&list[j]);
    __syncthreads();
    if (tid == 0) g_cnt[t] = 0;         // restore zero state for next call

    const float inv = 1.0f / (float)S_IMG;
    const float pxc = 1.0f - (2.0f * col + 1.0f) * inv;
    const float pyc = 1.0f - (2.0f * row + 1.0f) * inv;

    // ---- hit collection: no sorting in the hot loop ----
    float hz[HCAP];
    float hd[HCAP];
    int   hi[HCAP];
    int   nh = 0;

    for (int j = 0; j < cnt; j++) {
        float4 q = sl[j];
        float ddx = pxc - q.x;
        float ddy = pyc - q.y;
        float d2  = fmaf(ddx, ddx, ddy * ddy);
        if (d2 < RAD2) {
            hz[nh] = q.z; hd[nh] = d2; hi[nh] = __float_as_int(q.w);
            nh++;
            if (nh == HCAP) {            // extremely rare: prune to 16 best
                sort_hits(hz, hd, hi, nh);
                nh = KHITS;
            }
        }
    }

    // ---- one sort over the few collected hits ----
    sort_hits(hz, hd, hi, nh);
    const int nk = min(nh, KHITS);

    // ---- front-to-back alpha compositing ----
    float T = 1.0f, r = 0.0f, g = 0.0f, bl = 0.0f;
    for (int k = 0; k < nk; k++) {
        float a = 1.0f - hd[k] * INV_RAD2;
        a = fminf(fmaxf(a, 0.0f), 1.0f);
        const float* c = colors + (size_t)(b * NPTS + hi[k]) * 3;
        float w = a * T;
        r  += w * c[0];
        g  += w * c[1];
        bl += w * c[2];
        T *= (1.0f - a);
    }

    o[0] = r; o[1] = g; o[2] = bl;
}

// ----------------------------------------------------------------- launch ---
extern "C" void kernel_launch(void* const* d_in, const int* in_sizes, int n_in,
                              void* d_out, int out_size) {
    const float* points = (const float*)d_in[0];
    const float* eye    = (const float*)d_in[1];
    const float* colors = (const float*)d_in[2];
    float* out          = (float*)d_out;

    const int B = in_sizes[1] / 3;     // eye is [B,3]

    project_bin_kernel<<<(B * NPTS) / 256, 256>>>(points, eye);

    dim3 grid(TILES_X, TILES_X, B);
    render_tiled_kernel<<<grid, 64>>>(colors, out);
}